// round 4
// baseline (speedup 1.0000x reference)
#include <cuda_runtime.h>
#include <math.h>

#define BB 32
#define HH 512
#define WW 512
#define CC 3
#define RR 9            // half-width
#define KK 19           // kernel size
#define TT 32           // output tile
#define HL (TT + 2*RR)  // 50: tile + halo
#define NTH 256
#define EPS 1e-4f

#define SMEM_FLOATS (CC*HL*HL + CC*HL*TT)   // 7500 + 4800 = 12300
#define SMEM_BYTES  (SMEM_FLOATS * 4)       // 49200 B

// scratch: centered = x0 - blur(x0), stored PLANAR [B][C][H][W]
__device__ float g_cent[(size_t)BB * CC * HH * WW];

__device__ __forceinline__ void gauss_w(float* w) {
    float s = 0.f;
#pragma unroll
    for (int i = 0; i < KK; i++) {
        float t = (float)(i - RR);
        w[i] = __expf(-0.5f * t * t);
        s += w[i];
    }
    float inv = 1.0f / s;
#pragma unroll
    for (int i = 0; i < KK; i++) w[i] *= inv;
}

#define SIN(c, r, xx) sin_[((c)*HL + (r))*HL + (xx)]
#define SHB(c, r, xx) sh_[((c)*HL + (r))*TT + (xx)]

// Horizontal blur pass over smem: 1200 tasks of 4 outputs each.
__device__ __forceinline__ void hpass(const float* __restrict__ sin_,
                                      float* __restrict__ sh_,
                                      const float* __restrict__ w, int tid) {
#pragma unroll
    for (int i = 0; i < 5; i++) {
        int t = tid + i * NTH;
        if (t < CC * HL * 8) {              // 1200
            int grp  = t & 7;               // 8 groups of 4 cols
            int rowc = t >> 3;              // 0..149
            int c    = (rowc >= 2 * HL) ? 2 : (rowc >= HL ? 1 : 0);
            int row  = rowc - c * HL;
            const float* sp = &sin_[((c) * HL + row) * HL + grp * 4];
            float a0 = 0.f, a1 = 0.f, a2 = 0.f, a3 = 0.f;
#pragma unroll
            for (int k = 0; k < 22; k++) {
                float v = sp[k];
                if (k < KK)               a0 = fmaf(w[k],     v, a0);
                if (k >= 1 && k - 1 < KK) a1 = fmaf(w[k - 1], v, a1);
                if (k >= 2 && k - 2 < KK) a2 = fmaf(w[k - 2], v, a2);
                if (k >= 3)               a3 = fmaf(w[k - 3], v, a3);
            }
            float* op = &sh_[((c) * HL + row) * TT + grp * 4];
            op[0] = a0; op[1] = a1; op[2] = a2; op[3] = a3;
        }
    }
}

// ---------------------------------------------------------------------------
// Kernel 1: centered = x0 - gaussian_blur(x0)   (separable, tiled)
// ---------------------------------------------------------------------------
__global__ __launch_bounds__(NTH)
void lcn_mean_kernel(const float* __restrict__ xg) {
    extern __shared__ float smem[];
    float* sin_ = smem;
    float* sh_  = smem + CC * HL * HL;

    const int tx0 = blockIdx.x * TT;
    const int ty0 = blockIdx.y * TT;
    const int b   = blockIdx.z;
    const int tid = threadIdx.x;
    const int warp = tid >> 5;
    const int lane = tid & 31;

    float w[KK];
    gauss_w(w);

    const float* xb = xg + (size_t)b * HH * WW * CC;

    // ---- load halo + deinterleave (warp per row, lane per pixel, no div)
    for (int row = warp; row < HL; row += 8) {
        int gy = ty0 - RR + row;
        bool rv = ((unsigned)gy < HH);
        const float* rp = xb + ((size_t)gy * WW + (tx0 - RR)) * CC;
#pragma unroll
        for (int s = 0; s < 2; s++) {
            int xx = lane + s * 32;
            if (xx < HL) {
                int gx = tx0 - RR + xx;
                float a0 = 0.f, a1 = 0.f, a2 = 0.f;
                if (rv && (unsigned)gx < WW) {
                    const float* p = rp + 3 * xx;
                    a0 = p[0]; a1 = p[1]; a2 = p[2];
                }
                SIN(0, row, xx) = a0;
                SIN(1, row, xx) = a1;
                SIN(2, row, xx) = a2;
            }
        }
    }
    __syncthreads();

    hpass(sin_, sh_, w, tid);
    __syncthreads();

    // ---- vertical pass: thread owns column lx, rows yb..yb+3
    const int lx = tid & 31;
    const int yb = (tid >> 5) * 4;
    float cent[CC][4];
#pragma unroll
    for (int c = 0; c < CC; c++) {
        const float* bp = &sh_[(c * HL + yb) * TT + lx];
        float acc[4] = {0.f, 0.f, 0.f, 0.f};
#pragma unroll
        for (int k = 0; k < 22; k++) {
            float v = bp[k * TT];
#pragma unroll
            for (int r = 0; r < 4; r++) {
                int j = k - r;
                if (j >= 0 && j < KK) acc[r] = fmaf(w[j], v, acc[r]);
            }
        }
#pragma unroll
        for (int r = 0; r < 4; r++)
            cent[c][r] = SIN(c, yb + r + RR, lx + RR) - acc[r];
    }

    // ---- store planar [B][C][H][W], coalesced
#pragma unroll
    for (int c = 0; c < CC; c++) {
        float* cb = g_cent + (((size_t)b * CC + c) * HH + (ty0 + yb)) * WW + (tx0 + lx);
#pragma unroll
        for (int r = 0; r < 4; r++)
            cb[(size_t)r * WW] = cent[c][r];
    }
}

// ---------------------------------------------------------------------------
// Kernel 2: var = blur(centered^2); out = centered/(sqrt(var)+eps) * mask
// ---------------------------------------------------------------------------
__global__ __launch_bounds__(NTH)
void lcn_out_kernel(const float* __restrict__ mask, float* __restrict__ out) {
    extern __shared__ float smem[];
    float* sin_ = smem;          // holds centered^2
    float* sh_  = smem + CC * HL * HL;

    const int tx0 = blockIdx.x * TT;
    const int ty0 = blockIdx.y * TT;
    const int b   = blockIdx.z;
    const int tid = threadIdx.x;
    const int warp = tid >> 5;
    const int lane = tid & 31;

    float w[KK];
    gauss_w(w);

    // ---- load centered halo (planar rows, contiguous), square on the fly
    for (int rc = warp; rc < CC * HL; rc += 8) {     // 150 row-copies
        int c   = (rc >= 2 * HL) ? 2 : (rc >= HL ? 1 : 0);
        int row = rc - c * HL;
        int gy  = ty0 - RR + row;
        bool rv = ((unsigned)gy < HH);
        const float* rp = g_cent + (((size_t)b * CC + c) * HH + gy) * WW + (tx0 - RR);
        float* sp = &SIN(c, row, 0);
#pragma unroll
        for (int s = 0; s < 2; s++) {
            int xx = lane + s * 32;
            if (xx < HL) {
                int gx = tx0 - RR + xx;
                float v = 0.f;
                if (rv && (unsigned)gx < WW) v = rp[xx];
                sp[xx] = v * v;
            }
        }
    }
    __syncthreads();

    hpass(sin_, sh_, w, tid);
    __syncthreads();

    // ---- vertical pass -> var -> output
    const int lx = tid & 31;
    const int yb = (tid >> 5) * 4;
    float res[CC][4];
#pragma unroll
    for (int c = 0; c < CC; c++) {
        const float* bp = &sh_[(c * HL + yb) * TT + lx];
        float acc[4] = {0.f, 0.f, 0.f, 0.f};
#pragma unroll
        for (int k = 0; k < 22; k++) {
            float v = bp[k * TT];
#pragma unroll
            for (int r = 0; r < 4; r++) {
                int j = k - r;
                if (j >= 0 && j < KK) acc[r] = fmaf(w[j], v, acc[r]);
            }
        }
        // centered (unsquared) re-read from global, L2-hot, coalesced
        const float* cb = g_cent + (((size_t)b * CC + c) * HH + (ty0 + yb)) * WW + (tx0 + lx);
#pragma unroll
        for (int r = 0; r < 4; r++) {
            float stdv = sqrtf(acc[r]) + EPS;
            res[c][r] = __fdividef(cb[(size_t)r * WW], stdv);
        }
    }

#pragma unroll
    for (int r = 0; r < 4; r++) {
        int gy = ty0 + yb + r;
        int gx = tx0 + lx;
        float m = mask[(size_t)(b * HH + gy) * WW + gx];
        size_t o = ((size_t)(b * HH + gy) * WW + gx) * CC;
        out[o + 0] = res[0][r] * m;
        out[o + 1] = res[1][r] * m;
        out[o + 2] = res[2][r] * m;
    }
}

// ---------------------------------------------------------------------------
extern "C" void kernel_launch(void* const* d_in, const int* in_sizes, int n_in,
                              void* d_out, int out_size) {
    const float* x0   = (const float*)d_in[0];
    const float* mask = (const float*)d_in[1];
    float* out = (float*)d_out;

    cudaFuncSetAttribute(lcn_mean_kernel,
                         cudaFuncAttributeMaxDynamicSharedMemorySize, SMEM_BYTES);
    cudaFuncSetAttribute(lcn_out_kernel,
                         cudaFuncAttributeMaxDynamicSharedMemorySize, SMEM_BYTES);

    dim3 grid(WW / TT, HH / TT, BB);
    lcn_mean_kernel<<<grid, NTH, SMEM_BYTES>>>(x0);
    lcn_out_kernel<<<grid, NTH, SMEM_BYTES>>>(mask, out);
}

// round 5
// speedup vs baseline: 1.5885x; 1.5885x over previous
#include <cuda_runtime.h>
#include <math.h>

#define BB 32
#define HH 512
#define WW 512
#define CC 3
#define RR 6              // truncated half-width (13 taps; dropped taps < 1e-11)
#define KK 13
#define TT 32             // output tile
#define HL (TT + 2*RR)    // 44
#define SPITCH 45         // sin pitch (bank-conflict-free)
#define HPITCH 33         // h-pass output pitch (bank-conflict-free)
#define NTH 256
#define EPS 1e-4f

// 13-tap Gaussian(std=1) weights normalized by the full 19-tap sum (matches
// reference separable normalization to ~1e-11).
#define WLIST { 6.0758833e-9f, 1.4867195e-6f, 1.3383022e-4f, 4.4318485e-3f, \
                5.3990967e-2f, 2.4197072e-1f, 3.9894228e-1f, 2.4197072e-1f, \
                5.3990967e-2f, 4.4318485e-3f, 1.3383022e-4f, 1.4867195e-6f, \
                6.0758833e-9f }

// scratch: centered = x0 - blur(x0), stored PLANAR [B][C][H][W]
__device__ float g_cent[(size_t)BB * CC * HH * WW];

// ---------------------------------------------------------------------------
// Horizontal pass: 176 tasks (44 rows x 4 groups of 8 outputs). SQ: square
// the input on the fly (for the variance blur).
// ---------------------------------------------------------------------------
template<bool SQ>
__device__ __forceinline__ void hpass(const float* __restrict__ sin_,
                                      float* __restrict__ sh_, int tid) {
    const float W[KK] = WLIST;
    if (tid < HL * 4) {
        int row = tid >> 2;
        int grp = tid & 3;
        const float* sp = sin_ + row * SPITCH + grp * 8;
        float a0=0.f,a1=0.f,a2=0.f,a3=0.f,a4=0.f,a5=0.f,a6=0.f,a7=0.f;
#pragma unroll
        for (int k = 0; k < KK + 7; k++) {          // 20 loads -> 8 outputs
            float v = sp[k];
            if (SQ) v *= v;
            if (k - 0 >= 0 && k - 0 < KK) a0 = fmaf(W[k - 0], v, a0);
            if (k - 1 >= 0 && k - 1 < KK) a1 = fmaf(W[k - 1], v, a1);
            if (k - 2 >= 0 && k - 2 < KK) a2 = fmaf(W[k - 2], v, a2);
            if (k - 3 >= 0 && k - 3 < KK) a3 = fmaf(W[k - 3], v, a3);
            if (k - 4 >= 0 && k - 4 < KK) a4 = fmaf(W[k - 4], v, a4);
            if (k - 5 >= 0 && k - 5 < KK) a5 = fmaf(W[k - 5], v, a5);
            if (k - 6 >= 0 && k - 6 < KK) a6 = fmaf(W[k - 6], v, a6);
            if (k - 7 >= 0 && k - 7 < KK) a7 = fmaf(W[k - 7], v, a7);
        }
        float* op = sh_ + row * HPITCH + grp * 8;
        op[0]=a0; op[1]=a1; op[2]=a2; op[3]=a3;
        op[4]=a4; op[5]=a5; op[6]=a6; op[7]=a7;
    }
}

// ---------------------------------------------------------------------------
// Kernel 1: centered = x0 - blur(x0). One channel at a time per block.
// ---------------------------------------------------------------------------
__global__ __launch_bounds__(NTH)
void lcn_mean_kernel(const float* __restrict__ xg) {
    __shared__ float sin_[HL * SPITCH];
    __shared__ float sh_[HL * HPITCH];
    const float W[KK] = WLIST;

    const int tx0 = blockIdx.x * TT;
    const int ty0 = blockIdx.y * TT;
    const int b   = blockIdx.z;
    const int tid  = threadIdx.x;
    const int warp = tid >> 5;
    const int lane = tid & 31;
    const int lx = tid & 31;
    const int yb = (tid >> 5) * 4;

    const float* xb = xg + (size_t)b * HH * WW * CC;

#pragma unroll 1
    for (int c = 0; c < CC; c++) {
        // ---- halo load (channel-strided; rows L1-hot across channel iters)
        for (int row = warp; row < HL; row += 8) {
            int gy = ty0 - RR + row;
            bool rv = ((unsigned)gy < HH);
            const float* rp = xb + ((size_t)gy * WW + (tx0 - RR)) * CC + c;
            float* sp = sin_ + row * SPITCH;
#pragma unroll
            for (int s = 0; s < 2; s++) {
                int xx = lane + s * 32;
                if (xx < HL) {
                    int gx = tx0 - RR + xx;
                    float v = 0.f;
                    if (rv && (unsigned)gx < WW) v = rp[3 * xx];
                    sp[xx] = v;
                }
            }
        }
        __syncthreads();

        hpass<false>(sin_, sh_, tid);
        __syncthreads();

        // ---- vertical pass: column lx, rows yb..yb+3
        float acc0=0.f, acc1=0.f, acc2=0.f, acc3=0.f;
#pragma unroll
        for (int k = 0; k < KK + 3; k++) {          // 16 loads -> 4 outputs
            float v = sh_[(yb + k) * HPITCH + lx];
            if (k - 0 >= 0 && k - 0 < KK) acc0 = fmaf(W[k - 0], v, acc0);
            if (k - 1 >= 0 && k - 1 < KK) acc1 = fmaf(W[k - 1], v, acc1);
            if (k - 2 >= 0 && k - 2 < KK) acc2 = fmaf(W[k - 2], v, acc2);
            if (k - 3 >= 0 && k - 3 < KK) acc3 = fmaf(W[k - 3], v, acc3);
        }
        float* cb = g_cent + (((size_t)b * CC + c) * HH + (ty0 + yb)) * WW + (tx0 + lx);
        cb[0 * (size_t)WW] = sin_[(yb + 0 + RR) * SPITCH + lx + RR] - acc0;
        cb[1 * (size_t)WW] = sin_[(yb + 1 + RR) * SPITCH + lx + RR] - acc1;
        cb[2 * (size_t)WW] = sin_[(yb + 2 + RR) * SPITCH + lx + RR] - acc2;
        cb[3 * (size_t)WW] = sin_[(yb + 3 + RR) * SPITCH + lx + RR] - acc3;
        __syncthreads();   // protect smem before next channel's load
    }
}

// ---------------------------------------------------------------------------
// Kernel 2: var = blur(centered^2); out = centered/(sqrt(var)+eps) * mask
// ---------------------------------------------------------------------------
__global__ __launch_bounds__(NTH)
void lcn_out_kernel(const float* __restrict__ mask, float* __restrict__ out) {
    __shared__ float sin_[HL * SPITCH];   // unsquared centered halo
    __shared__ float sh_[HL * HPITCH];
    const float W[KK] = WLIST;

    const int tx0 = blockIdx.x * TT;
    const int ty0 = blockIdx.y * TT;
    const int b   = blockIdx.z;
    const int tid  = threadIdx.x;
    const int warp = tid >> 5;
    const int lane = tid & 31;
    const int lx = tid & 31;
    const int yb = (tid >> 5) * 4;

    float res[CC][4];

#pragma unroll 1
    for (int c = 0; c < CC; c++) {
        // ---- halo load from planar centered (fully coalesced rows)
        for (int row = warp; row < HL; row += 8) {
            int gy = ty0 - RR + row;
            bool rv = ((unsigned)gy < HH);
            const float* rp = g_cent + (((size_t)b * CC + c) * HH + gy) * WW + (tx0 - RR);
            float* sp = sin_ + row * SPITCH;
#pragma unroll
            for (int s = 0; s < 2; s++) {
                int xx = lane + s * 32;
                if (xx < HL) {
                    int gx = tx0 - RR + xx;
                    float v = 0.f;
                    if (rv && (unsigned)gx < WW) v = rp[xx];
                    sp[xx] = v;
                }
            }
        }
        __syncthreads();

        hpass<true>(sin_, sh_, tid);   // squares on the fly
        __syncthreads();

        // ---- vertical pass -> var -> res
        float acc0=0.f, acc1=0.f, acc2=0.f, acc3=0.f;
#pragma unroll
        for (int k = 0; k < KK + 3; k++) {
            float v = sh_[(yb + k) * HPITCH + lx];
            if (k - 0 >= 0 && k - 0 < KK) acc0 = fmaf(W[k - 0], v, acc0);
            if (k - 1 >= 0 && k - 1 < KK) acc1 = fmaf(W[k - 1], v, acc1);
            if (k - 2 >= 0 && k - 2 < KK) acc2 = fmaf(W[k - 2], v, acc2);
            if (k - 3 >= 0 && k - 3 < KK) acc3 = fmaf(W[k - 3], v, acc3);
        }
        res[c][0] = __fdividef(sin_[(yb + 0 + RR) * SPITCH + lx + RR], sqrtf(acc0) + EPS);
        res[c][1] = __fdividef(sin_[(yb + 1 + RR) * SPITCH + lx + RR], sqrtf(acc1) + EPS);
        res[c][2] = __fdividef(sin_[(yb + 2 + RR) * SPITCH + lx + RR], sqrtf(acc2) + EPS);
        res[c][3] = __fdividef(sin_[(yb + 3 + RR) * SPITCH + lx + RR], sqrtf(acc3) + EPS);
        __syncthreads();   // protect smem before next channel's load
    }

    // ---- mask + interleaved output (contiguous 384B span per warp)
#pragma unroll
    for (int r = 0; r < 4; r++) {
        int gy = ty0 + yb + r;
        int gx = tx0 + lx;
        float m = mask[(size_t)(b * HH + gy) * WW + gx];
        size_t o = ((size_t)(b * HH + gy) * WW + gx) * CC;
        out[o + 0] = res[0][r] * m;
        out[o + 1] = res[1][r] * m;
        out[o + 2] = res[2][r] * m;
    }
}

// ---------------------------------------------------------------------------
extern "C" void kernel_launch(void* const* d_in, const int* in_sizes, int n_in,
                              void* d_out, int out_size) {
    const float* x0   = (const float*)d_in[0];
    const float* mask = (const float*)d_in[1];
    float* out = (float*)d_out;

    dim3 grid(WW / TT, HH / TT, BB);
    lcn_mean_kernel<<<grid, NTH>>>(x0);
    lcn_out_kernel<<<grid, NTH>>>(mask, out);
}

// round 8
// speedup vs baseline: 2.0176x; 1.2701x over previous
#include <cuda_runtime.h>
#include <math.h>

#define BB 32
#define HH 512
#define WW 512
#define CC 3
#define RR 6              // truncated half-width (13 taps)
#define KK 13
#define TT 32             // output tile
#define HL (TT + 2*RR)    // 44
#define SPITCH 52         // smem input pitch (floats, mult of 4 for float4)
#define HPITCH 36         // h-out pitch (floats, mult of 4)
#define NTH 256
#define EPS 1e-4f

// padded centered scratch: rows 6+512+6=524, row stride 528, origin (6,6).
// Borders never written -> stay zero (device globals are zero-initialized).
#define PH 524
#define PW 528

// 13-tap Gaussian(std=1) weights normalized by the full 19-tap sum.
#define WLIST { 6.0758833e-9f, 1.4867195e-6f, 1.3383022e-4f, 4.4318485e-3f, \
                5.3990967e-2f, 2.4197072e-1f, 3.9894228e-1f, 2.4197072e-1f, \
                5.3990967e-2f, 4.4318485e-3f, 1.3383022e-4f, 1.4867195e-6f, \
                6.0758833e-9f }

__device__ float g_cent[(size_t)BB * CC * PH * PW];

// ---------------------------------------------------------------------------
// Horizontal pass: 176 tasks (44 rows x 4 groups of 8 outputs), float4 I/O.
// ---------------------------------------------------------------------------
template<bool SQ>
__device__ __forceinline__ void hpass(const float* __restrict__ sin_,
                                      float* __restrict__ sh_, int tid) {
    const float W[KK] = WLIST;
    if (tid < HL * 4) {
        int row = tid >> 2;
        int grp = tid & 3;
        const float4* sp = (const float4*)(sin_ + row * SPITCH) + grp * 2;
        float a[24];
#pragma unroll
        for (int q = 0; q < 6; q++) {
            float4 v = sp[q];
            a[4*q+0] = v.x; a[4*q+1] = v.y; a[4*q+2] = v.z; a[4*q+3] = v.w;
        }
        if (SQ) {
#pragma unroll
            for (int k = 0; k < 20; k++) a[k] *= a[k];
        }
        float acc[8];
#pragma unroll
        for (int o = 0; o < 8; o++) acc[o] = 0.f;
#pragma unroll
        for (int k = 0; k < 20; k++) {
#pragma unroll
            for (int o = 0; o < 8; o++) {
                int j = k - o;
                if (j >= 0 && j < KK) acc[o] = fmaf(W[j], a[k], acc[o]);
            }
        }
        float4* op = (float4*)(sh_ + row * HPITCH) + grp * 2;
        op[0] = make_float4(acc[0], acc[1], acc[2], acc[3]);
        op[1] = make_float4(acc[4], acc[5], acc[6], acc[7]);
    }
}

// ---------------------------------------------------------------------------
// Kernel 1: centered = x0 - blur(x0); writes interior of padded g_cent.
// ---------------------------------------------------------------------------
__global__ __launch_bounds__(NTH)
void lcn_mean_kernel(const float* __restrict__ xg) {
    __shared__ float sin_[HL * SPITCH];
    __shared__ float sh_[HL * HPITCH];
    const float W[KK] = WLIST;

    const int tx0 = blockIdx.x * TT;
    const int ty0 = blockIdx.y * TT;
    const int b   = blockIdx.z;
    const int tid  = threadIdx.x;
    const int warp = tid >> 5;
    const int lane = tid & 31;
    const int lx = tid & 31;
    const int yb = (tid >> 5) * 4;

    const float* xb = xg + (size_t)b * HH * WW * CC;
    const bool interior = (blockIdx.x > 0) && (blockIdx.x < 15) &&
                          (blockIdx.y > 0) && (blockIdx.y < 15);

#pragma unroll 1
    for (int c = 0; c < CC; c++) {
        if (interior) {
            // predicate-free halo load (deinterleave channel c)
            for (int row = warp; row < HL; row += 8) {
                const float* rp = xb + ((size_t)(ty0 - RR + row) * WW + (tx0 - RR)) * CC + c;
                float* sp = sin_ + row * SPITCH;
                sp[lane] = rp[3 * lane];
                if (lane < HL - 32) sp[lane + 32] = rp[3 * (lane + 32)];
            }
        } else {
            for (int row = warp; row < HL; row += 8) {
                int gy = ty0 - RR + row;
                bool rv = ((unsigned)gy < HH);
                const float* rp = xb + ((size_t)gy * WW + (tx0 - RR)) * CC + c;
                float* sp = sin_ + row * SPITCH;
#pragma unroll
                for (int s = 0; s < 2; s++) {
                    int xx = lane + s * 32;
                    if (xx < HL) {
                        int gx = tx0 - RR + xx;
                        float v = 0.f;
                        if (rv && (unsigned)gx < WW) v = rp[3 * xx];
                        sp[xx] = v;
                    }
                }
            }
        }
        __syncthreads();

        hpass<false>(sin_, sh_, tid);
        __syncthreads();

        // vertical pass: column lx, rows yb..yb+3
        float acc0 = 0.f, acc1 = 0.f, acc2 = 0.f, acc3 = 0.f;
#pragma unroll
        for (int k = 0; k < KK + 3; k++) {
            float v = sh_[(yb + k) * HPITCH + lx];
            if (k - 0 >= 0 && k - 0 < KK) acc0 = fmaf(W[k - 0], v, acc0);
            if (k - 1 >= 0 && k - 1 < KK) acc1 = fmaf(W[k - 1], v, acc1);
            if (k - 2 >= 0 && k - 2 < KK) acc2 = fmaf(W[k - 2], v, acc2);
            if (k - 3 >= 0 && k - 3 < KK) acc3 = fmaf(W[k - 3], v, acc3);
        }
        // store to padded g_cent (origin 6,6), coalesced
        float* cb = g_cent + ((size_t)(b * CC + c) * PH + (ty0 + yb + RR)) * PW
                    + (tx0 + lx + RR);
        cb[0 * (size_t)PW] = sin_[(yb + 0 + RR) * SPITCH + lx + RR] - acc0;
        cb[1 * (size_t)PW] = sin_[(yb + 1 + RR) * SPITCH + lx + RR] - acc1;
        cb[2 * (size_t)PW] = sin_[(yb + 2 + RR) * SPITCH + lx + RR] - acc2;
        cb[3 * (size_t)PW] = sin_[(yb + 3 + RR) * SPITCH + lx + RR] - acc3;
        __syncthreads();
    }
}

// ---------------------------------------------------------------------------
// Kernel 2: var = blur(centered^2); out = centered/(sqrt(var)+eps) * mask
// ---------------------------------------------------------------------------
__global__ __launch_bounds__(NTH)
void lcn_out_kernel(const float* __restrict__ mask, float* __restrict__ out) {
    __shared__ float sin_[HL * SPITCH];   // unsquared centered halo
    __shared__ float sh_[HL * HPITCH];
    const float W[KK] = WLIST;

    const int tx0 = blockIdx.x * TT;
    const int ty0 = blockIdx.y * TT;
    const int b   = blockIdx.z;
    const int tid = threadIdx.x;
    const int lx = tid & 31;
    const int yb = (tid >> 5) * 4;

    float res[CC][4];

#pragma unroll 1
    for (int c = 0; c < CC; c++) {
        // halo load: pure float4 copies, no bounds checks (zero-padded gmem).
        // 44 rows x 12 float4 (48 floats: halo 44 + 4 over-read, in-bounds).
        for (int f = tid; f < HL * 12; f += NTH) {
            int row = f / 12;
            int seg = f - row * 12;
            const float4* gp = (const float4*)(g_cent +
                ((size_t)(b * CC + c) * PH + (ty0 + row)) * PW) + 8 * blockIdx.x;
            *((float4*)(sin_ + row * SPITCH) + seg) = gp[seg];
        }
        __syncthreads();

        hpass<true>(sin_, sh_, tid);   // squares on the fly
        __syncthreads();

        // vertical pass -> var -> res
        float acc0 = 0.f, acc1 = 0.f, acc2 = 0.f, acc3 = 0.f;
#pragma unroll
        for (int k = 0; k < KK + 3; k++) {
            float v = sh_[(yb + k) * HPITCH + lx];
            if (k - 0 >= 0 && k - 0 < KK) acc0 = fmaf(W[k - 0], v, acc0);
            if (k - 1 >= 0 && k - 1 < KK) acc1 = fmaf(W[k - 1], v, acc1);
            if (k - 2 >= 0 && k - 2 < KK) acc2 = fmaf(W[k - 2], v, acc2);
            if (k - 3 >= 0 && k - 3 < KK) acc3 = fmaf(W[k - 3], v, acc3);
        }
        res[c][0] = __fdividef(sin_[(yb + 0 + RR) * SPITCH + lx + RR], sqrtf(acc0) + EPS);
        res[c][1] = __fdividef(sin_[(yb + 1 + RR) * SPITCH + lx + RR], sqrtf(acc1) + EPS);
        res[c][2] = __fdividef(sin_[(yb + 2 + RR) * SPITCH + lx + RR], sqrtf(acc2) + EPS);
        res[c][3] = __fdividef(sin_[(yb + 3 + RR) * SPITCH + lx + RR], sqrtf(acc3) + EPS);
        __syncthreads();
    }

    // mask + interleaved output
#pragma unroll
    for (int r = 0; r < 4; r++) {
        int gy = ty0 + yb + r;
        int gx = tx0 + lx;
        float m = mask[(size_t)(b * HH + gy) * WW + gx];
        size_t o = ((size_t)(b * HH + gy) * WW + gx) * CC;
        out[o + 0] = res[0][r] * m;
        out[o + 1] = res[1][r] * m;
        out[o + 2] = res[2][r] * m;
    }
}

// ---------------------------------------------------------------------------
extern "C" void kernel_launch(void* const* d_in, const int* in_sizes, int n_in,
                              void* d_out, int out_size) {
    const float* x0   = (const float*)d_in[0];
    const float* mask = (const float*)d_in[1];
    float* out = (float*)d_out;

    dim3 grid(WW / TT, HH / TT, BB);
    lcn_mean_kernel<<<grid, NTH>>>(x0);
    lcn_out_kernel<<<grid, NTH>>>(mask, out);
}